// round 15
// baseline (speedup 1.0000x reference)
#include <cuda_runtime.h>
#include <cuda_fp16.h>
#include <cstdint>

#define BB 16
#define CC 128
#define HH 128
#define WW 128
#define SDIM 512
#define PITCH 80              // smem pitch per px row (64B data + 16B pad) -> ldm conflict-free

// smem layout (bytes): two B strips (double buffered)
#define SB_ROW (PCW_ * PITCH)         // per strip row
#define PCW_ 130
#define SB_HL  (3 * SB_ROW)           // 31200 per strip
#define SMEMSZ (2 * SB_HL)            // 62400

// device scratch (allocation-free rule)
// weights in mma-A fragment order: [b][ch][tap][mt16(8)][ks(2)][lane(32)][8 halves]
__device__ __half g_wf[(size_t)BB * 4 * 9 * 8 * 2 * 32 * 8];
__device__ float  g_s[BB * CC];

// ---- helpers ----
static __device__ __forceinline__ uint32_t smem_u32(const void* p){
    uint32_t a; asm("{ .reg .u64 t; cvta.to.shared.u64 t, %1; cvt.u32.u64 %0, t; }":"=r"(a):"l"(p)); return a; }
static __device__ __forceinline__ void ldm4(uint32_t* r, uint32_t addr){
    asm volatile("ldmatrix.sync.aligned.m8n8.x4.shared.b16 {%0,%1,%2,%3}, [%4];"
                 : "=r"(r[0]),"=r"(r[1]),"=r"(r[2]),"=r"(r[3]) : "r"(addr)); }
static __device__ __forceinline__ void mma16816(float* c, const uint32_t* a, uint32_t b0, uint32_t b1){
    asm volatile("mma.sync.aligned.m16n8k16.row.col.f32.f16.f16.f32 "
                 "{%0,%1,%2,%3},{%4,%5,%6,%7},{%8,%9},{%0,%1,%2,%3};"
                 : "+f"(c[0]),"+f"(c[1]),"+f"(c[2]),"+f"(c[3])
                 : "r"(a[0]),"r"(a[1]),"r"(a[2]),"r"(a[3]),"r"(b0),"r"(b1)); }

// ---------------- kernel 1: modulation scalars ----------------
__global__ void modulate_kernel(const float* __restrict__ style, const float* __restrict__ mod_w,
                                const float* __restrict__ mod_b){
    const int gw = blockIdx.x*8 + (threadIdx.x>>5), lane = threadIdx.x&31;
    const int b = gw>>7, i = gw&127;
    const float* st = style + b*SDIM;
    const float* mw = mod_w + i*SDIM;
    float acc = 0.f;
#pragma unroll
    for (int d = 0; d < SDIM/32; d++) acc += st[d*32+lane]*mw[d*32+lane];
#pragma unroll
    for (int o = 16; o > 0; o >>= 1) acc += __shfl_xor_sync(~0u, acc, o);
    if (lane==0) g_s[b*CC+i] = acc*0.044194173824159216f + mod_b[i];
}

// ---------------- kernel 2: weights -> fp16 mma-fragment layout ----------------
__global__ void weight_kernel(const float* __restrict__ weight){
    const int o = blockIdx.x, b = blockIdx.y, i = threadIdx.x;  // i = ci
    const float s = g_s[b*CC+i] * 0.029462782549439483f;  // 1/sqrt(1152)
    float wm[9]; float sq = 0.f;
#pragma unroll
    for (int t = 0; t < 9; t++){ float w = weight[(o*CC+i)*9+t]*s; wm[t]=w; sq += w*w; }
    __shared__ float red[4];
#pragma unroll
    for (int off = 16; off > 0; off >>= 1) sq += __shfl_xor_sync(~0u, sq, off);
    if ((i&31)==0) red[i>>5]=sq;
    __syncthreads();
    const float demod = rsqrtf(red[0]+red[1]+red[2]+red[3]+1e-8f);

    const int ch   = i >> 5;
    const int i32  = i & 31;
    const int ks   = i32 >> 4;
    const int k16  = i32 & 15;
    const int regk = k16 >> 3;
    const int lm4  = (k16 & 7) >> 1;
    const int bit  = k16 & 1;
    const int m16  = o & 15, mt16 = o >> 4;
    const int regm = m16 >> 3;
    const int lane = (m16 & 7)*4 + lm4;
    const int reg  = regm + 2*regk;

#pragma unroll
    for (int t = 0; t < 9; t++){
        size_t di = ((((((size_t)(b*4+ch)*9 + t)*8 + mt16)*2 + ks)*32 + lane)*8) + reg*2 + bit;
        g_wf[di] = __float2half_rn(wm[t]*demod);
    }
}

// unit u (0..17): ky=u/6, ks=(u/3)%2, kx=u%3
#define U_KY(u) ((u)/6)
#define U_KS(u) (((u)/3)%2)
#define U_KX(u) ((u)%3)

// ---------------- kernel 3: conv; fused fp32->fp16 staging, fragment-aligned ldm ----------------
__global__ void __launch_bounds__(256, 2) conv_kernel(const float* __restrict__ x,
                                                      float* __restrict__ out){
    extern __shared__ __align__(1024) char sm[];
    const uint32_t sb = smem_u32(sm);
    const int b = blockIdx.y, y = blockIdx.x;
    const int tid = threadIdx.x, wid = tid>>5, lane = tid&31;
    const int m0w = wid & 3;
    const int n0 = (wid>>2)*64;
    // fragment-aligned mapping: B pairs land in consecutive LDSM dest regs (no MOVs)
    const int row_off = (lane & 7) + ((lane >> 4) << 3);
    const int kb16    = ((lane >> 3) & 1) * 16;
    const uint32_t bBase = sb + (n0 + row_off)*PITCH + kb16;
    const __half* wfLane = g_wf + (size_t)b*4*9*4096 + (size_t)lane*8 + (size_t)m0w*1024;
    const float* xb = x + (size_t)b*CC*HH*WW;

    float acc[2][8][4];
#pragma unroll
    for (int mt=0; mt<2; mt++)
#pragma unroll
        for (int nt=0; nt<8; nt++)
#pragma unroll
            for (int j=0; j<4; j++) acc[mt][nt][j] = 0.f;

    // ---- staging: fp32 NCHW -> fp16 strip [row][px(130)][ci32], pads zeroed ----
    // e decomposed px-fastest for coalesced LDG.32; half2 stores (ci pair).
    auto stage = [&](int ch, int bufsel){
        const float* xc = xb + (size_t)ch*32*HH*WW;
        char* dstb = sm + bufsel*SB_HL;
#pragma unroll 5
        for (int e = tid; e < 6240; e += 256){
            int row = e / 2080, rem = e % 2080;
            int ci2 = rem / 130, px = rem - ci2*130;
            int gy = y - 1 + row, gx = px - 1;
            bool ok = (gy >= 0) && (gy < HH) && (gx >= 0) && (gx < WW);
            const float* p0 = xc + ((size_t)(2*ci2)*HH + gy)*WW + gx;
            float v0 = ok ? p0[0] : 0.f;
            float v1 = ok ? p0[(size_t)HH*WW] : 0.f;
            *(__half2*)(dstb + row*SB_ROW + px*PITCH + ci2*4) = __floats2half2_rn(v0, v1);
        }
    };

    stage(0, 0);   // strip(ch0) -> buf0

    uint32_t bf[2][4][4];
    uint4    aw[2][2];

#pragma unroll 1
    for (int ch = 0; ch < 4; ch++){
        __syncthreads();   // strip(ch) stores visible to all warps

        if (ch < 3) stage(ch+1, (ch+1)&1);   // LDG/STS overlap with this chunk's MMAs

        const uint32_t stripB = bBase + ((uint32_t)(ch&1))*SB_HL;
        const __half* wfc = wfLane + (size_t)ch*9*4096;

        // load unit 0 fragments
#pragma unroll
        for (int np = 0; np < 4; np++)
            ldm4(bf[0][np], stripB + U_KY(0)*SB_ROW + (np*16 + U_KX(0))*PITCH + U_KS(0)*32);
#pragma unroll
        for (int mt = 0; mt < 2; mt++)
            aw[0][mt] = *(const uint4*)(wfc + (U_KY(0)*3+U_KX(0))*4096 + mt*512 + U_KS(0)*256);

#pragma unroll
        for (int u = 0; u < 18; u++){
            const int cur = u & 1, nxt = cur ^ 1;
            if (u < 17){
                const int v = u + 1;
#pragma unroll
                for (int np = 0; np < 4; np++)
                    ldm4(bf[nxt][np], stripB + U_KY(v)*SB_ROW + (np*16 + U_KX(v))*PITCH + U_KS(v)*32);
#pragma unroll
                for (int mt = 0; mt < 2; mt++)
                    aw[nxt][mt] = *(const uint4*)(wfc + (U_KY(v)*3+U_KX(v))*4096 + mt*512 + U_KS(v)*256);
            }
            // B pairs: (r0,r1)=nLo/(kLo,kHi), (r2,r3)=nHi
#pragma unroll
            for (int mt = 0; mt < 2; mt++){
                const uint32_t* a = (const uint32_t*)&aw[cur][mt];
#pragma unroll
                for (int np = 0; np < 4; np++){
                    mma16816(acc[mt][np*2+0], a, bf[cur][np][0], bf[cur][np][1]);
                    mma16816(acc[mt][np*2+1], a, bf[cur][np][2], bf[cur][np][3]);
                }
            }
        }
    }

    // ---- epilogue ----
#pragma unroll
    for (int mt = 0; mt < 2; mt++)
#pragma unroll
        for (int nt = 0; nt < 8; nt++){
            int m = m0w*32 + mt*16 + (lane>>2);
            int n = n0 + nt*8 + (lane&3)*2;
            float* p = out + (((size_t)(b*CC + m))*HH + y)*WW + n;
            *(float2*)p = make_float2(acc[mt][nt][0], acc[mt][nt][1]);
            *(float2*)(p + (size_t)8*HH*WW) = make_float2(acc[mt][nt][2], acc[mt][nt][3]);
        }
}

// ---------------------------------------------------------------------------
extern "C" void kernel_launch(void* const* d_in, const int* in_sizes, int n_in,
                              void* d_out, int out_size){
    const float* x      = (const float*)d_in[0];
    const float* style  = (const float*)d_in[1];
    const float* weight = (const float*)d_in[2];
    const float* mod_w  = (const float*)d_in[3];
    const float* mod_b  = (const float*)d_in[4];
    float* out = (float*)d_out;

    cudaFuncSetAttribute(conv_kernel, cudaFuncAttributeMaxDynamicSharedMemorySize, SMEMSZ);

    modulate_kernel<<<BB*CC/8, 256>>>(style, mod_w, mod_b);
    weight_kernel<<<dim3(CC, BB), CC>>>(weight);
    conv_kernel<<<dim3(HH, BB), 256, SMEMSZ>>>(x, out);
}

// round 16
// speedup vs baseline: 1.1404x; 1.1404x over previous
#include <cuda_runtime.h>
#include <cuda_fp16.h>
#include <cstdint>

#define BB 16
#define CC 128
#define HH 128
#define WW 128
#define SDIM 512
#define PCW 130              // padded width in gmem NHWC layout
#define XROWB 64             // bytes per px per 32-ci chunk (32 * half)
#define PITCH 80             // smem pitch per px row -> ldm conflict-free

// smem layout (bytes): two B strips (double buffered)
#define SB_ROW (PCW * PITCH)          // 10400 per strip row
#define SB_HL  (3 * SB_ROW)           // 31200 per strip
#define SMEMSZ (2 * SB_HL)            // 62400

// device scratch (allocation-free rule)
__device__ __half g_x[(size_t)BB * 4 * HH * PCW * 32];   // NHWC fp16, padded W
// weights in mma-A fragment order: [b][ch][tap][mt16(8)][ks(2)][lane(32)][8 halves]
__device__ __half g_wf[(size_t)BB * 4 * 9 * 8 * 2 * 32 * 8];
__device__ float  g_s[BB * CC];

// ---- helpers ----
static __device__ __forceinline__ uint32_t smem_u32(const void* p){
    uint32_t a; asm("{ .reg .u64 t; cvta.to.shared.u64 t, %1; cvt.u32.u64 %0, t; }":"=r"(a):"l"(p)); return a; }
static __device__ __forceinline__ void cp16(uint32_t d, const void* s, uint32_t sz){
    asm volatile("cp.async.cg.shared.global [%0], [%1], 16, %2;"::"r"(d),"l"(s),"r"(sz)); }
static __device__ __forceinline__ void cp_commit(){ asm volatile("cp.async.commit_group;"); }
static __device__ __forceinline__ void cp_wait0(){ asm volatile("cp.async.wait_group 0;":::"memory"); }
static __device__ __forceinline__ void ldm4(uint32_t* r, uint32_t addr){
    asm volatile("ldmatrix.sync.aligned.m8n8.x4.shared.b16 {%0,%1,%2,%3}, [%4];"
                 : "=r"(r[0]),"=r"(r[1]),"=r"(r[2]),"=r"(r[3]) : "r"(addr)); }
static __device__ __forceinline__ void mma16816(float* c, const uint32_t* a, uint32_t b0, uint32_t b1){
    asm volatile("mma.sync.aligned.m16n8k16.row.col.f32.f16.f16.f32 "
                 "{%0,%1,%2,%3},{%4,%5,%6,%7},{%8,%9},{%0,%1,%2,%3};"
                 : "+f"(c[0]),"+f"(c[1]),"+f"(c[2]),"+f"(c[3])
                 : "r"(a[0]),"r"(a[1]),"r"(a[2]),"r"(a[3]),"r"(b0),"r"(b1)); }

// ---------------- kernel 1: modulation scalars ----------------
__global__ void modulate_kernel(const float* __restrict__ style, const float* __restrict__ mod_w,
                                const float* __restrict__ mod_b){
    const int gw = blockIdx.x*8 + (threadIdx.x>>5), lane = threadIdx.x&31;
    const int b = gw>>7, i = gw&127;
    const float* st = style + b*SDIM;
    const float* mw = mod_w + i*SDIM;
    float acc = 0.f;
#pragma unroll
    for (int d = 0; d < SDIM/32; d++) acc += st[d*32+lane]*mw[d*32+lane];
#pragma unroll
    for (int o = 16; o > 0; o >>= 1) acc += __shfl_xor_sync(~0u, acc, o);
    if (lane==0) g_s[b*CC+i] = acc*0.044194173824159216f + mod_b[i];
}

// ---------------- kernel 2: weights -> fp16 mma-fragment layout ----------------
__global__ void weight_kernel(const float* __restrict__ weight){
    const int o = blockIdx.x, b = blockIdx.y, i = threadIdx.x;  // i = ci
    const float s = g_s[b*CC+i] * 0.029462782549439483f;  // 1/sqrt(1152)
    float wm[9]; float sq = 0.f;
#pragma unroll
    for (int t = 0; t < 9; t++){ float w = weight[(o*CC+i)*9+t]*s; wm[t]=w; sq += w*w; }
    __shared__ float red[4];
#pragma unroll
    for (int off = 16; off > 0; off >>= 1) sq += __shfl_xor_sync(~0u, sq, off);
    if ((i&31)==0) red[i>>5]=sq;
    __syncthreads();
    const float demod = rsqrtf(red[0]+red[1]+red[2]+red[3]+1e-8f);

    const int ch   = i >> 5;
    const int i32  = i & 31;
    const int ks   = i32 >> 4;
    const int k16  = i32 & 15;
    const int regk = k16 >> 3;
    const int lm4  = (k16 & 7) >> 1;
    const int bit  = k16 & 1;
    const int m16  = o & 15, mt16 = o >> 4;
    const int regm = m16 >> 3;
    const int lane = (m16 & 7)*4 + lm4;
    const int reg  = regm + 2*regk;

#pragma unroll
    for (int t = 0; t < 9; t++){
        size_t di = ((((((size_t)(b*4+ch)*9 + t)*8 + mt16)*2 + ks)*32 + lane)*8) + reg*2 + bit;
        g_wf[di] = __float2half_rn(wm[t]*demod);
    }
}

// ---------------- kernel 3: x NCHW fp32 -> padded NHWC fp16 (512 thr, float4 loads) ----------------
__global__ void convert_kernel(const float* __restrict__ x){
    __shared__ float tile[64][129];
    const int y = blockIdx.x, b = blockIdx.y, tid = threadIdx.x;
    if (tid < 256){   // zero pad columns px=0 and px=129 for all 4 chunks
        int ch = tid>>6, pc = ((tid>>5)&1) ? 129 : 0, ci = tid&31;
        size_t di = (((size_t)((b*4+ch)*HH + y))*PCW + pc)*32 + ci;
        g_x[di] = __float2half_rn(0.f);
    }
#pragma unroll
    for (int half_ = 0; half_ < 2; half_++){
        __syncthreads();
        // load 64 ci x 128 px as float4 (2048 vec loads / 512 thr = 4 each)
        for (int e = tid; e < 2048; e += 512){
            int ci = e >> 5, c4 = (e & 31) * 4;
            float4 v = *(const float4*)&x[(((size_t)(b*CC + half_*64 + ci))*HH + y)*WW + c4];
            tile[ci][c4+0] = v.x; tile[ci][c4+1] = v.y;
            tile[ci][c4+2] = v.z; tile[ci][c4+3] = v.w;
        }
        __syncthreads();
        // store half2 (4096 / 512 = 8 each), coalesced
        for (int e = tid; e < 4096; e += 512){
            int c = e>>5, cp = e&31;
            __half2 h = __floats2half2_rn(tile[2*cp][c], tile[2*cp+1][c]);
            int ch = half_*2 + (cp>>4);
            size_t di = (((size_t)((b*4+ch)*HH + y))*PCW + (c+1))*32 + 2*(cp&15);
            *(__half2*)&g_x[di] = h;
        }
    }
}

// unit u (0..17): ky=u/6, ks=(u/3)%2, kx=u%3
#define U_KY(u) ((u)/6)
#define U_KS(u) (((u)/3)%2)
#define U_KX(u) ((u)%3)

// ---------------- kernel 4: conv; A prefetch distance 2, B JIT ----------------
__global__ void __launch_bounds__(256, 2) conv_kernel(float* __restrict__ out){
    extern __shared__ __align__(1024) char sm[];
    const uint32_t sb = smem_u32(sm);
    const int b = blockIdx.y, y = blockIdx.x;
    const int tid = threadIdx.x, wid = tid>>5, lane = tid&31;
    const int m0w = wid & 3;
    const int n0 = (wid>>2)*64;
    // fragment-aligned mapping: B pairs land in consecutive LDSM dest regs (no MOVs)
    const int row_off = (lane & 7) + ((lane >> 4) << 3);
    const int kb16    = ((lane >> 3) & 1) * 16;
    const uint32_t bBase = sb + (n0 + row_off)*PITCH + kb16;
    const __half* wfLane = g_wf + (size_t)b*4*9*4096 + (size_t)lane*8 + (size_t)m0w*1024;

    float acc[2][8][4];
#pragma unroll
    for (int mt=0; mt<2; mt++)
#pragma unroll
        for (int nt=0; nt<8; nt++)
#pragma unroll
            for (int j=0; j<4; j++) acc[mt][nt][j] = 0.f;

    // ---- prologue: stage B strip(ch0) -> buf0 ----
    for (int e = tid; e < 1560; e += 256){
        int row = e / 520, q = e % 520;
        int px = q >> 2, c = q & 3;
        int gy = y - 1 + row;
        uint32_t val = (gy >= 0 && gy < HH) ? 16u : 0u;
        int gyc = gy < 0 ? 0 : (gy > 127 ? 127 : gy);
        const char* src = (const char*)g_x + ((((size_t)(b*4)*HH + gyc)*PCW + px)*XROWB) + c*16;
        cp16(sb + row*SB_ROW + px*PITCH + c*16, src, val);
    }
    cp_commit();

    uint32_t bf[4][4];   // single-unit B fragments (JIT, smem latency only)
    uint4    aw[3][2];   // A fragments, prefetch distance 2

#pragma unroll 1
    for (int ch = 0; ch < 4; ch++){
        cp_wait0();
        __syncthreads();   // strip(ch) visible

        if (ch < 3){
            for (int e = tid; e < 1560; e += 256){
                int row = e / 520, q = e % 520;
                int px = q >> 2, c = q & 3;
                int gy = y - 1 + row;
                uint32_t val = (gy >= 0 && gy < HH) ? 16u : 0u;
                int gyc = gy < 0 ? 0 : (gy > 127 ? 127 : gy);
                const char* src = (const char*)g_x
                    + ((((size_t)(b*4+ch+1)*HH + gyc)*PCW + px)*XROWB) + c*16;
                cp16(sb + ((ch+1)&1)*SB_HL + row*SB_ROW + px*PITCH + c*16, src, val);
            }
            cp_commit();
        }

        const uint32_t stripB = bBase + ((uint32_t)(ch&1))*SB_HL;
        const __half* wfc = wfLane + (size_t)ch*9*4096;

        // A prologue: units 0 and 1
#pragma unroll
        for (int mt = 0; mt < 2; mt++){
            aw[0][mt] = *(const uint4*)(wfc + (U_KY(0)*3+U_KX(0))*4096 + mt*512 + U_KS(0)*256);
            aw[1][mt] = *(const uint4*)(wfc + (U_KY(1)*3+U_KX(1))*4096 + mt*512 + U_KS(1)*256);
        }

#pragma unroll
        for (int u = 0; u < 18; u++){
            // B fragments for this unit (smem, 29-cyc latency covered by issue below)
#pragma unroll
            for (int np = 0; np < 4; np++)
                ldm4(bf[np], stripB + U_KY(u)*SB_ROW + (np*16 + U_KX(u))*PITCH + U_KS(u)*32);
            // A fragments two units ahead
            if (u < 16){
                const int v = u + 2;
#pragma unroll
                for (int mt = 0; mt < 2; mt++)
                    aw[v%3][mt] = *(const uint4*)(wfc + (U_KY(v)*3+U_KX(v))*4096 + mt*512 + U_KS(v)*256);
            }
            // mma: B pairs (r0,r1)=nLo/(kLo,kHi), (r2,r3)=nHi
#pragma unroll
            for (int mt = 0; mt < 2; mt++){
                const uint32_t* a = (const uint32_t*)&aw[u%3][mt];
#pragma unroll
                for (int np = 0; np < 4; np++){
                    mma16816(acc[mt][np*2+0], a, bf[np][0], bf[np][1]);
                    mma16816(acc[mt][np*2+1], a, bf[np][2], bf[np][3]);
                }
            }
        }
    }

    // ---- epilogue ----
#pragma unroll
    for (int mt = 0; mt < 2; mt++)
#pragma unroll
        for (int nt = 0; nt < 8; nt++){
            int m = m0w*32 + mt*16 + (lane>>2);
            int n = n0 + nt*8 + (lane&3)*2;
            float* p = out + (((size_t)(b*CC + m))*HH + y)*WW + n;
            *(float2*)p = make_float2(acc[mt][nt][0], acc[mt][nt][1]);
            *(float2*)(p + (size_t)8*HH*WW) = make_float2(acc[mt][nt][2], acc[mt][nt][3]);
        }
}

// ---------------------------------------------------------------------------
extern "C" void kernel_launch(void* const* d_in, const int* in_sizes, int n_in,
                              void* d_out, int out_size){
    const float* x      = (const float*)d_in[0];
    const float* style  = (const float*)d_in[1];
    const float* weight = (const float*)d_in[2];
    const float* mod_w  = (const float*)d_in[3];
    const float* mod_b  = (const float*)d_in[4];
    float* out = (float*)d_out;

    cudaFuncSetAttribute(conv_kernel, cudaFuncAttributeMaxDynamicSharedMemorySize, SMEMSZ);

    modulate_kernel<<<BB*CC/8, 256>>>(style, mod_w, mod_b);
    weight_kernel<<<dim3(CC, BB), CC>>>(weight);
    convert_kernel<<<dim3(HH, BB), 512>>>(x);
    conv_kernel<<<dim3(HH, BB), 256, SMEMSZ>>>(out);
}